// round 12
// baseline (speedup 1.0000x reference)
#include <cuda_runtime.h>
#include <cuda_fp16.h>
#include <math.h>
#include <stdint.h>

// ---------------------------------------------------------------------------
// Problem constants
// ---------------------------------------------------------------------------
constexpr int BATCH   = 2;
constexpr int SEQ     = 2048;
constexpr int DMODEL  = 2048;
constexpr int DFF     = 8192;
constexpr int NHEADS  = 16;
constexpr int NKV     = 8;
constexpr int HD      = 128;
constexpr int DKV     = NKV * HD;      // 1024
constexpr int TOK     = BATCH * SEQ;   // 4096
constexpr float EPSV  = 1e-5f;
constexpr float SM_SCALE = 0.08838834764831845f; // 128^-0.5

typedef __half f16;

// ---------------------------------------------------------------------------
// Scratch (device globals; allocation anywhere is forbidden)
// ---------------------------------------------------------------------------
__device__ f16   g_x1h [(size_t)TOK * DMODEL];
__device__ f16   g_qh  [(size_t)TOK * DMODEL];   // rope'd Q (fp16)
__device__ f16   g_kh  [(size_t)TOK * DKV];      // rope'd K (fp16)
__device__ float g_v   [(size_t)TOK * DKV];
__device__ f16   g_vth [(size_t)TOK * DKV];      // V^T: [(b*8+kh)][128][SEQ]
__device__ f16   g_sc  [(size_t)BATCH * NHEADS * SEQ * SEQ];  // 268 MB
__device__ f16   g_ph  [(size_t)BATCH * NHEADS * SEQ * SEQ];
__device__ f16   g_ctxh[(size_t)TOK * DMODEL];
__device__ float g_h2  [(size_t)TOK * DMODEL];
__device__ f16   g_x2h [(size_t)TOK * DMODEL];
__device__ f16   g_g16 [(size_t)TOK * DFF];
__device__ f16   g_mh  [(size_t)TOK * DFF];
// transposed fp16 weights: [N, K]
__device__ f16   g_wqt[(size_t)DMODEL * DMODEL];
__device__ f16   g_wkt[(size_t)DKV * DMODEL];
__device__ f16   g_wvt[(size_t)DKV * DMODEL];
__device__ f16   g_wot[(size_t)DMODEL * DMODEL];
__device__ f16   g_wgt[(size_t)DFF * DMODEL];
__device__ f16   g_wut[(size_t)DFF * DMODEL];
__device__ f16   g_wdt[(size_t)DMODEL * DFF];

// ---------------------------------------------------------------------------
// Fast exp: FFMA-only (no MUFU). rel err ~2e-6 for x in [-80, 80].
// exp(x) = 2^(x*log2e); n = rint(y) via magic add; 2^f deg-5 Taylor;
// 2^n injected into exponent bits.
// ---------------------------------------------------------------------------
__device__ __forceinline__ float fexpf(float x) {
    x = fmaxf(x, -80.0f);
    float t = fmaf(x, 1.4426950408889634f, 12582912.0f); // 1.5*2^23 magic
    float n = t - 12582912.0f;
    float f = fmaf(x, 1.4426950408889634f, -n);          // [-0.5, 0.5]
    float p = 1.3333558146e-3f;
    p = fmaf(p, f, 9.6181291076e-3f);
    p = fmaf(p, f, 5.5504108665e-2f);
    p = fmaf(p, f, 2.4022650696e-1f);
    p = fmaf(p, f, 6.9314718056e-1f);
    p = fmaf(p, f, 1.0f);
    return __int_as_float(__float_as_int(p) + (((int)n) << 23));
}

// ---------------------------------------------------------------------------
// PTX helpers — baseline sm_80+ only (harness targets plain sm_103)
// ---------------------------------------------------------------------------
__device__ __forceinline__ uint32_t smem_u32(const void* p) {
    uint32_t a;
    asm("{ .reg .u64 t; cvta.to.shared.u64 t, %1; cvt.u32.u64 %0, t; }"
        : "=r"(a) : "l"(p));
    return a;
}

__device__ __forceinline__ void cp16(uint32_t saddr, const void* g) {
    unsigned long long ga = (unsigned long long)__cvta_generic_to_global(g);
    asm volatile("cp.async.cg.shared.global [%0], [%1], 16;\n"
                 :: "r"(saddr), "l"(ga));
}
#define CP_COMMIT() asm volatile("cp.async.commit_group;\n" ::: "memory")
template <int N>
__device__ __forceinline__ void cp_wait() {
    asm volatile("cp.async.wait_group %0;\n" :: "n"(N) : "memory");
}

__device__ __forceinline__ void ldmx4(uint32_t* r, uint32_t addr) {
    asm volatile("ldmatrix.sync.aligned.m8n8.x4.shared.b16 {%0,%1,%2,%3}, [%4];\n"
        : "=r"(r[0]), "=r"(r[1]), "=r"(r[2]), "=r"(r[3]) : "r"(addr));
}

__device__ __forceinline__ void mma16816h(float* c, const uint32_t* a, const uint32_t* b) {
    asm volatile(
        "mma.sync.aligned.m16n8k16.row.col.f32.f16.f16.f32 "
        "{%0,%1,%2,%3}, {%4,%5,%6,%7}, {%8,%9}, {%0,%1,%2,%3};\n"
        : "+f"(c[0]), "+f"(c[1]), "+f"(c[2]), "+f"(c[3])
        : "r"(a[0]), "r"(a[1]), "r"(a[2]), "r"(a[3]), "r"(b[0]), "r"(b[1]));
}

constexpr int LDSS = 80;                 // smem row stride bytes (32 f16 + pad)

// ===========================================================================
// 256-thread fp16 GEMM: C[128 x 256] tile of A[M,K] * Bt[N,K]^T (+R)
// 8 warps in 2x4, warp tile 64x64, BK=32, 3-stage cp.async, 1 CTA/SM.
// OB=0: fp32 out (+residual). OB=1: fp16 out. OB=2: fp16 + fused RoPE.
// OB=3: fp16 out = silu(G) * result (fused SwiGLU).
// ===========================================================================
constexpr int AB2   = 128 * LDSS;        // 10240
constexpr int BB2   = 256 * LDSS;        // 20480
constexpr int STG2  = AB2 + BB2;         // 30720
constexpr int SM2   = 3 * STG2;          // 92160

__device__ __forceinline__ void load_stage_2(
    uint32_t sb, int s, const f16* __restrict__ A, const f16* __restrict__ B,
    long lda, long ldb, int k0, int tid)
{
    uint32_t base = sb + (uint32_t)(s * STG2);
    #pragma unroll
    for (int i = 0; i < 2; i++) {
        int idx = tid + i * 256;                 // 0..511
        int r = idx >> 2, cb = (idx & 3) << 4;
        cp16(base + (uint32_t)(r * LDSS + cb), A + (long)r * lda + k0 + (cb >> 1));
    }
    #pragma unroll
    for (int i = 0; i < 4; i++) {
        int idx = tid + i * 256;                 // 0..1023
        int r = idx >> 2, cb = (idx & 3) << 4;
        cp16(base + (uint32_t)(AB2 + r * LDSS + cb), B + (long)r * ldb + k0 + (cb >> 1));
    }
}

__device__ __forceinline__ void compute_stage_2(
    uint32_t sb, int s, int wm, int wn, int l, float acc[4][8][4])
{
    uint32_t As = sb + (uint32_t)(s * STG2);
    uint32_t Bs = As + AB2;
    uint32_t a_off = (uint32_t)((wm * 64 + (l & 15)) * LDSS + ((l >> 4) << 4));
    uint32_t b_off = (uint32_t)((wn * 64 + ((l >> 4) << 3) + (l & 7)) * LDSS
                                + (((l >> 3) & 1) << 4));
    #pragma unroll
    for (int kk = 0; kk < 2; kk++) {
        uint32_t kb = (uint32_t)(kk * 32);
        uint32_t ah[4][4], bh[8][2];
        #pragma unroll
        for (int m = 0; m < 4; m++)
            ldmx4(ah[m], As + a_off + m * (16 * LDSS) + kb);
        #pragma unroll
        for (int p = 0; p < 4; p++) {
            uint32_t r[4];
            ldmx4(r, Bs + b_off + p * (16 * LDSS) + kb);
            bh[2*p][0] = r[0]; bh[2*p][1] = r[1];
            bh[2*p+1][0] = r[2]; bh[2*p+1][1] = r[3];
        }
        #pragma unroll
        for (int m = 0; m < 4; m++)
            #pragma unroll
            for (int n = 0; n < 8; n++)
                mma16816h(acc[m][n], ah[m], bh[n]);
    }
}

template <int OB>
__device__ __forceinline__ void gemm256(
    const f16* __restrict__ a, long lda, const f16* __restrict__ b, long ldb,
    const float* __restrict__ R, void* __restrict__ Cv, long ldc,
    int K, int m0, int n0,
    const float* __restrict__ cs, const float* __restrict__ sn,
    const f16* __restrict__ G)
{
    constexpr int S = 3;
    extern __shared__ char smem[];
    uint32_t sb = smem_u32(smem);
    const int tid = threadIdx.x, wid = tid >> 5, l = tid & 31;
    const int wm = wid & 1, wn = wid >> 1;   // 2 x 4

    const f16* A = a + (long)m0 * lda;
    const f16* B = b + (long)n0 * ldb;

    float acc[4][8][4];
    #pragma unroll
    for (int m = 0; m < 4; m++)
        #pragma unroll
        for (int n = 0; n < 8; n++)
            #pragma unroll
            for (int i = 0; i < 4; i++) acc[m][n][i] = 0.f;

    const int nk = K >> 5;
    #pragma unroll
    for (int c = 0; c < S - 1; c++) {
        load_stage_2(sb, c, A, B, lda, ldb, c * 32, tid);
        CP_COMMIT();
    }
    int slot_c = 0, slot_p = S - 1;
    for (int c = 0; c < nk; c++) {
        cp_wait<S - 2>();
        __syncthreads();
        if (c + S - 1 < nk)
            load_stage_2(sb, slot_p, A, B, lda, ldb, (c + S - 1) * 32, tid);
        CP_COMMIT();
        compute_stage_2(sb, slot_c, wm, wn, l, acc);
        slot_c = (slot_c + 1 == S) ? 0 : slot_c + 1;
        slot_p = (slot_p + 1 == S) ? 0 : slot_p + 1;
    }

    const int row0 = m0 + wm * 64, col0 = n0 + wn * 64;
    #pragma unroll
    for (int m = 0; m < 4; m++) {
        int r0 = row0 + m * 16 + (l >> 2);
        #pragma unroll
        for (int n = 0; n < 8; n++) {
            int cc = col0 + n * 8 + (l & 3) * 2;   // even global column
            float2 v0 = make_float2(acc[m][n][0], acc[m][n][1]);
            float2 v1 = make_float2(acc[m][n][2], acc[m][n][3]);
            if (OB == 0) {
                float* C = (float*)Cv;
                if (R) {
                    float2 q0 = *(const float2*)(R + (long)r0 * ldc + cc);
                    float2 q1 = *(const float2*)(R + (long)(r0 + 8) * ldc + cc);
                    v0.x += q0.x; v0.y += q0.y; v1.x += q1.x; v1.y += q1.y;
                }
                *(float2*)(C + (long)r0 * ldc + cc)       = v0;
                *(float2*)(C + (long)(r0 + 8) * ldc + cc) = v1;
            } else if (OB == 1) {
                f16* C = (f16*)Cv;
                __half2 h0, h1;
                h0.x = __float2half(v0.x); h0.y = __float2half(v0.y);
                h1.x = __float2half(v1.x); h1.y = __float2half(v1.y);
                *(__half2*)(C + (long)r0 * ldc + cc)       = h0;
                *(__half2*)(C + (long)(r0 + 8) * ldc + cc) = h1;
            } else if (OB == 2) {
                // fused RoPE. cc even; (v.x, v.y) = (x[2j], x[2j+1]) of head.
                f16* C = (f16*)Cv;
                int hb = cc & ~127;
                int j  = (cc & 127) >> 1;
                float c0 = cs[(long)r0 * 64 + j];
                float s0 = sn[(long)r0 * 64 + j];
                C[(long)r0 * ldc + hb + j]      = __float2half(v0.x * c0 - v0.y * s0);
                C[(long)r0 * ldc + hb + 64 + j] = __float2half(v0.x * s0 + v0.y * c0);
                float c1 = cs[(long)(r0 + 8) * 64 + j];
                float s1 = sn[(long)(r0 + 8) * 64 + j];
                C[(long)(r0 + 8) * ldc + hb + j]      = __float2half(v1.x * c1 - v1.y * s1);
                C[(long)(r0 + 8) * ldc + hb + 64 + j] = __float2half(v1.x * s1 + v1.y * c1);
            } else {
                // OB == 3: out = silu(G) * result  (fast exp, no MUFU)
                f16* C = (f16*)Cv;
                __half2 gp0 = *(const __half2*)(G + (long)r0 * ldc + cc);
                __half2 gp1 = *(const __half2*)(G + (long)(r0 + 8) * ldc + cc);
                float g0 = __half2float(gp0.x), g1 = __half2float(gp0.y);
                float g2 = __half2float(gp1.x), g3 = __half2float(gp1.y);
                __half2 h0, h1;
                h0.x = __float2half(v0.x * g0 / (1.0f + fexpf(-g0)));
                h0.y = __float2half(v0.y * g1 / (1.0f + fexpf(-g1)));
                h1.x = __float2half(v1.x * g2 / (1.0f + fexpf(-g2)));
                h1.y = __float2half(v1.y * g3 / (1.0f + fexpf(-g3)));
                *(__half2*)(C + (long)r0 * ldc + cc)       = h0;
                *(__half2*)(C + (long)(r0 + 8) * ldc + cc) = h1;
            }
        }
    }
}

// ---------------------------------------------------------------------------
// 256-thread GEMM wrapper kernels
// ---------------------------------------------------------------------------
__global__ __launch_bounds__(256, 1) void g256_f32out_kernel(
    const f16* a, long lda, const f16* b, long ldb,
    const float* R, float* C, long ldc, int K)
{
    gemm256<0>(a, lda, b, ldb, R, C, ldc, K,
               blockIdx.y * 128, blockIdx.x * 256, nullptr, nullptr, nullptr);
}

__global__ __launch_bounds__(256, 1) void g256_f16out_kernel(
    const f16* a, long lda, const f16* b, long ldb, f16* C, long ldc, int K)
{
    gemm256<1>(a, lda, b, ldb, nullptr, C, ldc, K,
               blockIdx.y * 128, blockIdx.x * 256, nullptr, nullptr, nullptr);
}

__global__ __launch_bounds__(256, 1) void g256_rope_kernel(
    const f16* a, long lda, const f16* b, long ldb,
    f16* C, long ldc, int K, const float* cs, const float* sn)
{
    gemm256<2>(a, lda, b, ldb, nullptr, C, ldc, K,
               blockIdx.y * 128, blockIdx.x * 256, cs, sn, nullptr);
}

__global__ __launch_bounds__(256, 1) void g256_silu_kernel(
    const f16* a, long lda, const f16* b, long ldb,
    f16* C, long ldc, int K, const f16* G)
{
    gemm256<3>(a, lda, b, ldb, nullptr, C, ldc, K,
               blockIdx.y * 128, blockIdx.x * 256, nullptr, nullptr, G);
}

__global__ __launch_bounds__(256, 1) void g256_scores_kernel()
{
    int z = blockIdx.z, b = z >> 4, h = z & 15, kh = h >> 1;
    const f16* A = g_qh + (long)b * SEQ * DMODEL + h * HD;
    const f16* B = g_kh + (long)b * SEQ * DKV + kh * HD;
    f16* C = g_sc + (long)z * SEQ * SEQ;
    gemm256<1>(A, DMODEL, B, DKV, nullptr, C, SEQ, HD,
               blockIdx.y * 128, blockIdx.x * 256, nullptr, nullptr, nullptr);
}

// ===========================================================================
// 128-thread fp16 GEMM (PV only; N=128 output per head)
// ===========================================================================
constexpr int MATB = 128 * LDSS;         // 10240
constexpr int SM1  = 3 * 2 * MATB;       // 61440

__device__ __forceinline__ void load_stage_h(
    uint32_t sb, int s, const f16* __restrict__ A, const f16* __restrict__ B,
    long lda, long ldb, int k0, int tid)
{
    uint32_t base = sb + (uint32_t)(s * 2 * MATB);
    #pragma unroll
    for (int i = 0; i < 4; i++) {
        int idx = tid + i * 128;
        int r = idx >> 2, cb = (idx & 3) << 4;
        uint32_t so = (uint32_t)(r * LDSS + cb);
        cp16(base + so,        A + (long)r * lda + k0 + (cb >> 1));
        cp16(base + MATB + so, B + (long)r * ldb + k0 + (cb >> 1));
    }
}

__device__ __forceinline__ void compute_stage_h(
    uint32_t sb, int s, int wm, int wn, int l, float acc[4][8][4])
{
    uint32_t As = sb + (uint32_t)(s * 2 * MATB);
    uint32_t Bs = As + MATB;
    uint32_t a_off = (uint32_t)((wm * 64 + (l & 15)) * LDSS + ((l >> 4) << 4));
    uint32_t b_off = (uint32_t)((wn * 64 + ((l >> 4) << 3) + (l & 7)) * LDSS
                                + (((l >> 3) & 1) << 4));
    #pragma unroll
    for (int kk = 0; kk < 2; kk++) {
        uint32_t kb = (uint32_t)(kk * 32);
        uint32_t ah[4][4], bh[8][2];
        #pragma unroll
        for (int m = 0; m < 4; m++)
            ldmx4(ah[m], As + a_off + m * (16 * LDSS) + kb);
        #pragma unroll
        for (int p = 0; p < 4; p++) {
            uint32_t r[4];
            ldmx4(r, Bs + b_off + p * (16 * LDSS) + kb);
            bh[2*p][0] = r[0]; bh[2*p][1] = r[1];
            bh[2*p+1][0] = r[2]; bh[2*p+1][1] = r[3];
        }
        #pragma unroll
        for (int m = 0; m < 4; m++)
            #pragma unroll
            for (int n = 0; n < 8; n++)
                mma16816h(acc[m][n], ah[m], bh[n]);
    }
}

__global__ __launch_bounds__(128) void gemm_pv_kernel()
{
    int z = blockIdx.z, b = z >> 4, h = z & 15, kh = h >> 1;
    const f16* A = g_ph + (long)z * SEQ * SEQ + (long)blockIdx.y * 128 * SEQ;
    const f16* B = g_vth + (long)(b * NKV + kh) * HD * SEQ;
    f16* C = g_ctxh + (long)b * SEQ * DMODEL + h * HD;

    constexpr int S = 3;
    extern __shared__ char smem[];
    uint32_t sb = smem_u32(smem);
    const int tid = threadIdx.x, wid = tid >> 5, l = tid & 31;
    const int wm = wid & 1, wn = wid >> 1;

    float acc[4][8][4];
    #pragma unroll
    for (int m = 0; m < 4; m++)
        #pragma unroll
        for (int n = 0; n < 8; n++)
            #pragma unroll
            for (int i = 0; i < 4; i++) acc[m][n][i] = 0.f;

    const int nk = SEQ >> 5;
    #pragma unroll
    for (int c = 0; c < S - 1; c++) {
        load_stage_h(sb, c, A, B, SEQ, SEQ, c * 32, tid);
        CP_COMMIT();
    }
    int slot_c = 0, slot_p = S - 1;
    for (int c = 0; c < nk; c++) {
        cp_wait<S - 2>();
        __syncthreads();
        if (c + S - 1 < nk)
            load_stage_h(sb, slot_p, A, B, SEQ, SEQ, (c + S - 1) * 32, tid);
        CP_COMMIT();
        compute_stage_h(sb, slot_c, wm, wn, l, acc);
        slot_c = (slot_c + 1 == S) ? 0 : slot_c + 1;
        slot_p = (slot_p + 1 == S) ? 0 : slot_p + 1;
    }

    const int row0 = blockIdx.y * 128 + wm * 64, col0 = wn * 64;
    #pragma unroll
    for (int m = 0; m < 4; m++) {
        int r0 = row0 + m * 16 + (l >> 2);
        #pragma unroll
        for (int n = 0; n < 8; n++) {
            int cc = col0 + n * 8 + (l & 3) * 2;
            __half2 h0, h1;
            h0.x = __float2half(acc[m][n][0]); h0.y = __float2half(acc[m][n][1]);
            h1.x = __float2half(acc[m][n][2]); h1.y = __float2half(acc[m][n][3]);
            *(__half2*)(C + (long)r0 * DMODEL + cc)       = h0;
            *(__half2*)(C + (long)(r0 + 8) * DMODEL + cc) = h1;
        }
    }
}

// ---------------------------------------------------------------------------
// Reductions
// ---------------------------------------------------------------------------
__device__ __forceinline__ float block_reduce_sum(float v)
{
    __shared__ float red[32];
    int lid = threadIdx.x & 31, wid = threadIdx.x >> 5;
    #pragma unroll
    for (int o = 16; o; o >>= 1) v += __shfl_xor_sync(0xffffffffu, v, o);
    if (lid == 0) red[wid] = v;
    __syncthreads();
    v = (threadIdx.x < 8) ? red[threadIdx.x] : 0.f;
    if (wid == 0) {
        #pragma unroll
        for (int o = 4; o; o >>= 1) v += __shfl_xor_sync(0xffffffffu, v, o);
        if (lid == 0) red[0] = v;
    }
    __syncthreads();
    return red[0];
}
__device__ __forceinline__ float block_reduce_max(float v)
{
    __shared__ float red[32];
    int lid = threadIdx.x & 31, wid = threadIdx.x >> 5;
    #pragma unroll
    for (int o = 16; o; o >>= 1) v = fmaxf(v, __shfl_xor_sync(0xffffffffu, v, o));
    if (lid == 0) red[wid] = v;
    __syncthreads();
    v = (threadIdx.x < 8) ? red[threadIdx.x] : -INFINITY;
    if (wid == 0) {
        #pragma unroll
        for (int o = 4; o; o >>= 1) v = fmaxf(v, __shfl_xor_sync(0xffffffffu, v, o));
        if (lid == 0) red[0] = v;
    }
    __syncthreads();
    return red[0];
}

// ---------------------------------------------------------------------------
// RMSNorm -> fp16
// ---------------------------------------------------------------------------
__global__ __launch_bounds__(256) void rmsnorm_f16_kernel(
    const float* __restrict__ x, const float* __restrict__ w,
    f16* __restrict__ oh)
{
    long row = blockIdx.x;
    const float* xr = x + row * DMODEL;
    float vals[8];
    float ss = 0.f;
    #pragma unroll
    for (int i = 0; i < 8; i++) {
        int idx = threadIdx.x + i * 256;
        vals[i] = xr[idx];
        ss = fmaf(vals[i], vals[i], ss);
    }
    float total = block_reduce_sum(ss);
    float rstd = rsqrtf(total * (1.0f / DMODEL) + EPSV);
    #pragma unroll
    for (int i = 0; i < 8; i++) {
        int idx = threadIdx.x + i * 256;
        oh[row * DMODEL + idx] = __float2half(vals[i] * rstd * w[idx]);
    }
}

// ---------------------------------------------------------------------------
// Weight transpose: in [RI, CI] fp32 -> out [CI, RI] fp16
// ---------------------------------------------------------------------------
__global__ __launch_bounds__(256) void transpose_f16_kernel(
    const float* __restrict__ in, f16* __restrict__ oh, int RI, int CI)
{
    __shared__ float t[32][33];
    int tx = threadIdx.x & 31, ty = threadIdx.x >> 5;
    int r0 = blockIdx.y * 32, c0 = blockIdx.x * 32;
    #pragma unroll
    for (int i = 0; i < 4; i++)
        t[ty + i * 8][tx] = in[(long)(r0 + ty + i * 8) * CI + c0 + tx];
    __syncthreads();
    #pragma unroll
    for (int i = 0; i < 4; i++)
        oh[(long)(c0 + ty + i * 8) * RI + r0 + tx] =
            __float2half(t[tx][ty + i * 8]);
}

// V transpose: g_v [b, s, kh*128+d] -> g_vth [(b*8+kh)][d][s] fp16
__global__ __launch_bounds__(256) void vT_kernel()
{
    __shared__ float t[32][33];
    int z = blockIdx.z;
    int b = z >> 3, kh = z & 7;
    const float* in = g_v + (long)b * SEQ * DKV + kh * HD;
    f16* oh = g_vth + (long)z * HD * SEQ;
    int tx = threadIdx.x & 31, ty = threadIdx.x >> 5;
    int s0 = blockIdx.y * 32, d0 = blockIdx.x * 32;
    #pragma unroll
    for (int i = 0; i < 4; i++)
        t[ty + i * 8][tx] = in[(long)(s0 + ty + i * 8) * DKV + d0 + tx];
    __syncthreads();
    #pragma unroll
    for (int i = 0; i < 4; i++)
        oh[(long)(d0 + ty + i * 8) * SEQ + s0 + tx] =
            __float2half(t[tx][ty + i * 8]);
}

// ---------------------------------------------------------------------------
// Softmax (scale + mask), fp16 in -> fp16 out. Fast exp (no MUFU).
// ---------------------------------------------------------------------------
__global__ __launch_bounds__(256) void softmax_kernel(const float* __restrict__ mask)
{
    int z = blockIdx.y;
    int b = z >> 4;
    long row = blockIdx.x;
    const f16* srow = g_sc + ((long)z * SEQ + row) * SEQ;
    const float* mrow = mask + ((long)b * SEQ + row) * SEQ;
    f16* phr = g_ph + ((long)z * SEQ + row) * SEQ;

    float v[8];
    float mx = -INFINITY;
    #pragma unroll
    for (int i = 0; i < 8; i++) {
        int idx = threadIdx.x + i * 256;
        v[i] = fmaf(__half2float(srow[idx]), SM_SCALE, mrow[idx]);
        mx = fmaxf(mx, v[i]);
    }
    float bm = block_reduce_max(mx);
    float sum = 0.f;
    #pragma unroll
    for (int i = 0; i < 8; i++) {
        v[i] = fexpf(v[i] - bm);
        sum += v[i];
    }
    float total = block_reduce_sum(sum);
    float inv = 1.0f / total;
    #pragma unroll
    for (int i = 0; i < 8; i++) {
        int idx = threadIdx.x + i * 256;
        phr[idx] = __float2half(v[i] * inv);
    }
}

// ---------------------------------------------------------------------------
// Launch
// ---------------------------------------------------------------------------
extern "C" void kernel_launch(void* const* d_in, const int* in_sizes, int n_in,
                              void* d_out, int out_size)
{
    const float* hs   = (const float*)d_in[0];
    const float* cosp = (const float*)d_in[1];
    const float* sinp = (const float*)d_in[2];
    const float* mask = (const float*)d_in[3];
    const float* wq   = (const float*)d_in[4];
    const float* wk   = (const float*)d_in[5];
    const float* wv   = (const float*)d_in[6];
    const float* wo   = (const float*)d_in[7];
    const float* wg   = (const float*)d_in[8];
    const float* wu   = (const float*)d_in[9];
    const float* wd   = (const float*)d_in[10];
    const float* ln1  = (const float*)d_in[11];
    const float* ln2  = (const float*)d_in[12];
    float* out = (float*)d_out;

    cudaFuncSetAttribute(g256_f32out_kernel,
                         cudaFuncAttributeMaxDynamicSharedMemorySize, SM2);
    cudaFuncSetAttribute(g256_f16out_kernel,
                         cudaFuncAttributeMaxDynamicSharedMemorySize, SM2);
    cudaFuncSetAttribute(g256_rope_kernel,
                         cudaFuncAttributeMaxDynamicSharedMemorySize, SM2);
    cudaFuncSetAttribute(g256_silu_kernel,
                         cudaFuncAttributeMaxDynamicSharedMemorySize, SM2);
    cudaFuncSetAttribute(g256_scores_kernel,
                         cudaFuncAttributeMaxDynamicSharedMemorySize, SM2);
    cudaFuncSetAttribute(gemm_pv_kernel,
                         cudaFuncAttributeMaxDynamicSharedMemorySize, SM1);

    f16 *x1h, *qh, *kh, *ctxh, *x2h, *g16, *mh;
    f16 *wqt, *wkt, *wvt, *wot, *wgt, *wut, *wdt;
    float *v, *h2;
    cudaGetSymbolAddress((void**)&x1h, g_x1h);
    cudaGetSymbolAddress((void**)&qh,  g_qh);
    cudaGetSymbolAddress((void**)&kh,  g_kh);
    cudaGetSymbolAddress((void**)&ctxh,g_ctxh);
    cudaGetSymbolAddress((void**)&x2h, g_x2h);
    cudaGetSymbolAddress((void**)&g16, g_g16);
    cudaGetSymbolAddress((void**)&mh,  g_mh);
    cudaGetSymbolAddress((void**)&wqt, g_wqt);
    cudaGetSymbolAddress((void**)&wkt, g_wkt);
    cudaGetSymbolAddress((void**)&wvt, g_wvt);
    cudaGetSymbolAddress((void**)&wot, g_wot);
    cudaGetSymbolAddress((void**)&wgt, g_wgt);
    cudaGetSymbolAddress((void**)&wut, g_wut);
    cudaGetSymbolAddress((void**)&wdt, g_wdt);
    cudaGetSymbolAddress((void**)&v,   g_v);
    cudaGetSymbolAddress((void**)&h2,  g_h2);

    // 1) x1 = rmsnorm(hs) -> fp16
    rmsnorm_f16_kernel<<<TOK, 256>>>(hs, ln1, x1h);

    // 2) weight transposes -> fp16 [N,K]
    transpose_f16_kernel<<<dim3(DMODEL/32, DMODEL/32), 256>>>(wq, wqt, DMODEL, DMODEL);
    transpose_f16_kernel<<<dim3(DKV/32,    DMODEL/32), 256>>>(wk, wkt, DMODEL, DKV);
    transpose_f16_kernel<<<dim3(DKV/32,    DMODEL/32), 256>>>(wv, wvt, DMODEL, DKV);
    transpose_f16_kernel<<<dim3(DMODEL/32, DMODEL/32), 256>>>(wo, wot, DMODEL, DMODEL);
    transpose_f16_kernel<<<dim3(DFF/32,    DMODEL/32), 256>>>(wg, wgt, DMODEL, DFF);
    transpose_f16_kernel<<<dim3(DFF/32,    DMODEL/32), 256>>>(wu, wut, DMODEL, DFF);
    transpose_f16_kernel<<<dim3(DMODEL/32, DFF/32),    256>>>(wd, wdt, DFF, DMODEL);

    // 3) Q/K projections with fused RoPE -> fp16; V projection -> fp32
    g256_rope_kernel<<<dim3(DMODEL/256, TOK/128), 256, SM2>>>(
        x1h, DMODEL, wqt, DMODEL, qh, DMODEL, DMODEL, cosp, sinp);
    g256_rope_kernel<<<dim3(DKV/256, TOK/128), 256, SM2>>>(
        x1h, DMODEL, wkt, DMODEL, kh, DKV, DMODEL, cosp, sinp);
    g256_f32out_kernel<<<dim3(DKV/256, TOK/128), 256, SM2>>>(
        x1h, DMODEL, wvt, DMODEL, nullptr, v, DKV, DMODEL);

    // 4) V transpose -> fp16
    vT_kernel<<<dim3(HD/32, SEQ/32, BATCH*NKV), 256>>>();

    // 5) scores = Q K^T -> fp16
    g256_scores_kernel<<<dim3(SEQ/256, SEQ/128, BATCH*NHEADS), 256, SM2>>>();

    // 6) softmax -> P fp16
    softmax_kernel<<<dim3(SEQ, BATCH*NHEADS), 256>>>(mask);

    // 7) ctx = P V -> fp16
    gemm_pv_kernel<<<dim3(1, SEQ/128, BATCH*NHEADS), 128, SM1>>>();

    // 8) h2 = hs + ctx @ wo
    g256_f32out_kernel<<<dim3(DMODEL/256, TOK/128), 256, SM2>>>(
        ctxh, DMODEL, wot, DMODEL, hs, h2, DMODEL, DMODEL);

    // 9) x2 = rmsnorm(h2) -> fp16
    rmsnorm_f16_kernel<<<TOK, 256>>>(h2, ln2, x2h);

    // 10) MLP: gate, then up with fused SwiGLU (fast exp)
    g256_f16out_kernel<<<dim3(DFF/256, TOK/128), 256, SM2>>>(
        x2h, DMODEL, wgt, DMODEL, g16, DFF, DMODEL);
    g256_silu_kernel<<<dim3(DFF/256, TOK/128), 256, SM2>>>(
        x2h, DMODEL, wut, DMODEL, mh, DFF, DMODEL, g16);

    // 11) out = h2 + m @ wd
    g256_f32out_kernel<<<dim3(DMODEL/256, TOK/128), 256, SM2>>>(
        mh, DFF, wdt, DFF, h2, out, DMODEL, DFF);
}

// round 14
// speedup vs baseline: 1.0021x; 1.0021x over previous
#include <cuda_runtime.h>
#include <cuda_fp16.h>
#include <math.h>
#include <stdint.h>

// ---------------------------------------------------------------------------
// Problem constants
// ---------------------------------------------------------------------------
constexpr int BATCH   = 2;
constexpr int SEQ     = 2048;
constexpr int DMODEL  = 2048;
constexpr int DFF     = 8192;
constexpr int NHEADS  = 16;
constexpr int NKV     = 8;
constexpr int HD      = 128;
constexpr int DKV     = NKV * HD;      // 1024
constexpr int TOK     = BATCH * SEQ;   // 4096
constexpr float EPSV  = 1e-5f;
constexpr float SM_SCALE = 0.08838834764831845f; // 128^-0.5

typedef __half f16;

// ---------------------------------------------------------------------------
// Scratch (device globals; allocation anywhere is forbidden)
// ---------------------------------------------------------------------------
__device__ f16   g_x1h [(size_t)TOK * DMODEL];
__device__ f16   g_qh  [(size_t)TOK * DMODEL];   // rope'd Q (fp16)
__device__ f16   g_kh  [(size_t)TOK * DKV];      // rope'd K (fp16)
__device__ float g_v   [(size_t)TOK * DKV];
__device__ f16   g_vth [(size_t)TOK * DKV];      // V^T: [(b*8+kh)][128][SEQ]
__device__ f16   g_sc  [(size_t)BATCH * NHEADS * SEQ * SEQ];  // 268 MB
__device__ f16   g_ph  [(size_t)BATCH * NHEADS * SEQ * SEQ];
__device__ f16   g_ctxh[(size_t)TOK * DMODEL];
__device__ float g_h2  [(size_t)TOK * DMODEL];
__device__ f16   g_x2h [(size_t)TOK * DMODEL];
__device__ f16   g_g16 [(size_t)TOK * DFF];
__device__ f16   g_mh  [(size_t)TOK * DFF];
// transposed fp16 weights: [N, K]
__device__ f16   g_wqt[(size_t)DMODEL * DMODEL];
__device__ f16   g_wkt[(size_t)DKV * DMODEL];
__device__ f16   g_wvt[(size_t)DKV * DMODEL];
__device__ f16   g_wot[(size_t)DMODEL * DMODEL];
__device__ f16   g_wgt[(size_t)DFF * DMODEL];
__device__ f16   g_wut[(size_t)DFF * DMODEL];
__device__ f16   g_wdt[(size_t)DMODEL * DFF];

// ---------------------------------------------------------------------------
// Fast exp: FFMA-only. rel err ~2e-6 for x in [-80, 80].
// ---------------------------------------------------------------------------
__device__ __forceinline__ float fexpf(float x) {
    x = fmaxf(x, -80.0f);
    float t = fmaf(x, 1.4426950408889634f, 12582912.0f); // 1.5*2^23 magic
    float n = t - 12582912.0f;
    float f = fmaf(x, 1.4426950408889634f, -n);          // [-0.5, 0.5]
    float p = 1.3333558146e-3f;
    p = fmaf(p, f, 9.6181291076e-3f);
    p = fmaf(p, f, 5.5504108665e-2f);
    p = fmaf(p, f, 2.4022650696e-1f);
    p = fmaf(p, f, 6.9314718056e-1f);
    p = fmaf(p, f, 1.0f);
    return __int_as_float(__float_as_int(p) + (((int)n) << 23));
}

// ---------------------------------------------------------------------------
// PTX helpers — baseline sm_80+ only (harness targets plain sm_103)
// ---------------------------------------------------------------------------
__device__ __forceinline__ uint32_t smem_u32(const void* p) {
    uint32_t a;
    asm("{ .reg .u64 t; cvta.to.shared.u64 t, %1; cvt.u32.u64 %0, t; }"
        : "=r"(a) : "l"(p));
    return a;
}

__device__ __forceinline__ void cp16(uint32_t saddr, const void* g) {
    unsigned long long ga = (unsigned long long)__cvta_generic_to_global(g);
    asm volatile("cp.async.cg.shared.global [%0], [%1], 16;\n"
                 :: "r"(saddr), "l"(ga));
}
#define CP_COMMIT() asm volatile("cp.async.commit_group;\n" ::: "memory")
template <int N>
__device__ __forceinline__ void cp_wait() {
    asm volatile("cp.async.wait_group %0;\n" :: "n"(N) : "memory");
}

__device__ __forceinline__ void ldmx4(uint32_t* r, uint32_t addr) {
    asm volatile("ldmatrix.sync.aligned.m8n8.x4.shared.b16 {%0,%1,%2,%3}, [%4];\n"
        : "=r"(r[0]), "=r"(r[1]), "=r"(r[2]), "=r"(r[3]) : "r"(addr));
}

__device__ __forceinline__ void mma16816h(float* c, const uint32_t* a, const uint32_t* b) {
    asm volatile(
        "mma.sync.aligned.m16n8k16.row.col.f32.f16.f16.f32 "
        "{%0,%1,%2,%3}, {%4,%5,%6,%7}, {%8,%9}, {%0,%1,%2,%3};\n"
        : "+f"(c[0]), "+f"(c[1]), "+f"(c[2]), "+f"(c[3])
        : "r"(a[0]), "r"(a[1]), "r"(a[2]), "r"(a[3]), "r"(b[0]), "r"(b[1]));
}

constexpr int LDSS = 80;                 // smem row stride bytes (32 f16 + pad)

// ===========================================================================
// 256-thread fp16 GEMM: C[128 x 256] tile of A[M,K] * Bt[N,K]^T (+R)
// 8 warps in 2x4, warp tile 64x64, BK=32, 3-stage cp.async, 1 CTA/SM.
// OB=0: fp32 out (+residual). OB=1: fp16 out. OB=2: fp16 + fused RoPE.
// OB=3: fp16 out = silu(G) * result (fused SwiGLU).
// ===========================================================================
constexpr int AB2   = 128 * LDSS;        // 10240
constexpr int BB2   = 256 * LDSS;        // 20480
constexpr int STG2  = AB2 + BB2;         // 30720
constexpr int SM2   = 3 * STG2;          // 92160

__device__ __forceinline__ void load_stage_2(
    uint32_t sb, int s, const f16* __restrict__ A, const f16* __restrict__ B,
    long lda, long ldb, int k0, int tid)
{
    uint32_t base = sb + (uint32_t)(s * STG2);
    #pragma unroll
    for (int i = 0; i < 2; i++) {
        int idx = tid + i * 256;                 // 0..511
        int r = idx >> 2, cb = (idx & 3) << 4;
        cp16(base + (uint32_t)(r * LDSS + cb), A + (long)r * lda + k0 + (cb >> 1));
    }
    #pragma unroll
    for (int i = 0; i < 4; i++) {
        int idx = tid + i * 256;                 // 0..1023
        int r = idx >> 2, cb = (idx & 3) << 4;
        cp16(base + (uint32_t)(AB2 + r * LDSS + cb), B + (long)r * ldb + k0 + (cb >> 1));
    }
}

__device__ __forceinline__ void compute_stage_2(
    uint32_t sb, int s, int wm, int wn, int l, float acc[4][8][4])
{
    uint32_t As = sb + (uint32_t)(s * STG2);
    uint32_t Bs = As + AB2;
    uint32_t a_off = (uint32_t)((wm * 64 + (l & 15)) * LDSS + ((l >> 4) << 4));
    uint32_t b_off = (uint32_t)((wn * 64 + ((l >> 4) << 3) + (l & 7)) * LDSS
                                + (((l >> 3) & 1) << 4));
    #pragma unroll
    for (int kk = 0; kk < 2; kk++) {
        uint32_t kb = (uint32_t)(kk * 32);
        uint32_t ah[4][4], bh[8][2];
        #pragma unroll
        for (int m = 0; m < 4; m++)
            ldmx4(ah[m], As + a_off + m * (16 * LDSS) + kb);
        #pragma unroll
        for (int p = 0; p < 4; p++) {
            uint32_t r[4];
            ldmx4(r, Bs + b_off + p * (16 * LDSS) + kb);
            bh[2*p][0] = r[0]; bh[2*p][1] = r[1];
            bh[2*p+1][0] = r[2]; bh[2*p+1][1] = r[3];
        }
        #pragma unroll
        for (int m = 0; m < 4; m++)
            #pragma unroll
            for (int n = 0; n < 8; n++)
                mma16816h(acc[m][n], ah[m], bh[n]);
    }
}

template <int OB>
__device__ __forceinline__ void gemm256(
    const f16* __restrict__ a, long lda, const f16* __restrict__ b, long ldb,
    const float* __restrict__ R, void* __restrict__ Cv, long ldc,
    int K, int m0, int n0,
    const float* __restrict__ cs, const float* __restrict__ sn,
    const f16* __restrict__ G)
{
    constexpr int S = 3;
    extern __shared__ char smem[];
    uint32_t sb = smem_u32(smem);
    const int tid = threadIdx.x, wid = tid >> 5, l = tid & 31;
    const int wm = wid & 1, wn = wid >> 1;   // 2 x 4

    const f16* A = a + (long)m0 * lda;
    const f16* B = b + (long)n0 * ldb;

    float acc[4][8][4];
    #pragma unroll
    for (int m = 0; m < 4; m++)
        #pragma unroll
        for (int n = 0; n < 8; n++)
            #pragma unroll
            for (int i = 0; i < 4; i++) acc[m][n][i] = 0.f;

    const int nk = K >> 5;
    #pragma unroll
    for (int c = 0; c < S - 1; c++) {
        load_stage_2(sb, c, A, B, lda, ldb, c * 32, tid);
        CP_COMMIT();
    }
    int slot_c = 0, slot_p = S - 1;
    for (int c = 0; c < nk; c++) {
        cp_wait<S - 2>();
        __syncthreads();
        if (c + S - 1 < nk)
            load_stage_2(sb, slot_p, A, B, lda, ldb, (c + S - 1) * 32, tid);
        CP_COMMIT();
        compute_stage_2(sb, slot_c, wm, wn, l, acc);
        slot_c = (slot_c + 1 == S) ? 0 : slot_c + 1;
        slot_p = (slot_p + 1 == S) ? 0 : slot_p + 1;
    }

    const int row0 = m0 + wm * 64, col0 = n0 + wn * 64;
    #pragma unroll
    for (int m = 0; m < 4; m++) {
        int r0 = row0 + m * 16 + (l >> 2);
        #pragma unroll
        for (int n = 0; n < 8; n++) {
            int cc = col0 + n * 8 + (l & 3) * 2;   // even global column
            float2 v0 = make_float2(acc[m][n][0], acc[m][n][1]);
            float2 v1 = make_float2(acc[m][n][2], acc[m][n][3]);
            if (OB == 0) {
                float* C = (float*)Cv;
                if (R) {
                    float2 q0 = *(const float2*)(R + (long)r0 * ldc + cc);
                    float2 q1 = *(const float2*)(R + (long)(r0 + 8) * ldc + cc);
                    v0.x += q0.x; v0.y += q0.y; v1.x += q1.x; v1.y += q1.y;
                }
                *(float2*)(C + (long)r0 * ldc + cc)       = v0;
                *(float2*)(C + (long)(r0 + 8) * ldc + cc) = v1;
            } else if (OB == 1) {
                f16* C = (f16*)Cv;
                __half2 h0, h1;
                h0.x = __float2half(v0.x); h0.y = __float2half(v0.y);
                h1.x = __float2half(v1.x); h1.y = __float2half(v1.y);
                *(__half2*)(C + (long)r0 * ldc + cc)       = h0;
                *(__half2*)(C + (long)(r0 + 8) * ldc + cc) = h1;
            } else if (OB == 2) {
                // fused RoPE. cc even; (v.x, v.y) = (x[2j], x[2j+1]) of head.
                f16* C = (f16*)Cv;
                int hb = cc & ~127;
                int j  = (cc & 127) >> 1;
                float c0 = cs[(long)r0 * 64 + j];
                float s0 = sn[(long)r0 * 64 + j];
                C[(long)r0 * ldc + hb + j]      = __float2half(v0.x * c0 - v0.y * s0);
                C[(long)r0 * ldc + hb + 64 + j] = __float2half(v0.x * s0 + v0.y * c0);
                float c1 = cs[(long)(r0 + 8) * 64 + j];
                float s1 = sn[(long)(r0 + 8) * 64 + j];
                C[(long)(r0 + 8) * ldc + hb + j]      = __float2half(v1.x * c1 - v1.y * s1);
                C[(long)(r0 + 8) * ldc + hb + 64 + j] = __float2half(v1.x * s1 + v1.y * c1);
            } else {
                // OB == 3: out = silu(G) * result  (fast exp)
                f16* C = (f16*)Cv;
                __half2 gp0 = *(const __half2*)(G + (long)r0 * ldc + cc);
                __half2 gp1 = *(const __half2*)(G + (long)(r0 + 8) * ldc + cc);
                float g0 = __half2float(gp0.x), g1 = __half2float(gp0.y);
                float g2 = __half2float(gp1.x), g3 = __half2float(gp1.y);
                __half2 h0, h1;
                h0.x = __float2half(v0.x * g0 / (1.0f + fexpf(-g0)));
                h0.y = __float2half(v0.y * g1 / (1.0f + fexpf(-g1)));
                h1.x = __float2half(v1.x * g2 / (1.0f + fexpf(-g2)));
                h1.y = __float2half(v1.y * g3 / (1.0f + fexpf(-g3)));
                *(__half2*)(C + (long)r0 * ldc + cc)       = h0;
                *(__half2*)(C + (long)(r0 + 8) * ldc + cc) = h1;
            }
        }
    }
}

// ---------------------------------------------------------------------------
// 256-thread GEMM wrapper kernels
// ---------------------------------------------------------------------------
__global__ __launch_bounds__(256, 1) void g256_f32out_kernel(
    const f16* a, long lda, const f16* b, long ldb,
    const float* R, float* C, long ldc, int K)
{
    gemm256<0>(a, lda, b, ldb, R, C, ldc, K,
               blockIdx.y * 128, blockIdx.x * 256, nullptr, nullptr, nullptr);
}

__global__ __launch_bounds__(256, 1) void g256_f16out_kernel(
    const f16* a, long lda, const f16* b, long ldb, f16* C, long ldc, int K)
{
    gemm256<1>(a, lda, b, ldb, nullptr, C, ldc, K,
               blockIdx.y * 128, blockIdx.x * 256, nullptr, nullptr, nullptr);
}

__global__ __launch_bounds__(256, 1) void g256_rope_kernel(
    const f16* a, long lda, const f16* b, long ldb,
    f16* C, long ldc, int K, const float* cs, const float* sn)
{
    gemm256<2>(a, lda, b, ldb, nullptr, C, ldc, K,
               blockIdx.y * 128, blockIdx.x * 256, cs, sn, nullptr);
}

__global__ __launch_bounds__(256, 1) void g256_silu_kernel(
    const f16* a, long lda, const f16* b, long ldb,
    f16* C, long ldc, int K, const f16* G)
{
    gemm256<3>(a, lda, b, ldb, nullptr, C, ldc, K,
               blockIdx.y * 128, blockIdx.x * 256, nullptr, nullptr, G);
}

__global__ __launch_bounds__(256, 1) void g256_scores_kernel()
{
    int z = blockIdx.z, b = z >> 4, h = z & 15, kh = h >> 1;
    const f16* A = g_qh + (long)b * SEQ * DMODEL + h * HD;
    const f16* B = g_kh + (long)b * SEQ * DKV + kh * HD;
    f16* C = g_sc + (long)z * SEQ * SEQ;
    gemm256<1>(A, DMODEL, B, DKV, nullptr, C, SEQ, HD,
               blockIdx.y * 128, blockIdx.x * 256, nullptr, nullptr, nullptr);
}

// ===========================================================================
// 128-thread fp16 GEMM (PV only; N=128 output per head)
// ===========================================================================
constexpr int MATB = 128 * LDSS;         // 10240
constexpr int SM1  = 3 * 2 * MATB;       // 61440

__device__ __forceinline__ void load_stage_h(
    uint32_t sb, int s, const f16* __restrict__ A, const f16* __restrict__ B,
    long lda, long ldb, int k0, int tid)
{
    uint32_t base = sb + (uint32_t)(s * 2 * MATB);
    #pragma unroll
    for (int i = 0; i < 4; i++) {
        int idx = tid + i * 128;
        int r = idx >> 2, cb = (idx & 3) << 4;
        uint32_t so = (uint32_t)(r * LDSS + cb);
        cp16(base + so,        A + (long)r * lda + k0 + (cb >> 1));
        cp16(base + MATB + so, B + (long)r * ldb + k0 + (cb >> 1));
    }
}

__device__ __forceinline__ void compute_stage_h(
    uint32_t sb, int s, int wm, int wn, int l, float acc[4][8][4])
{
    uint32_t As = sb + (uint32_t)(s * 2 * MATB);
    uint32_t Bs = As + MATB;
    uint32_t a_off = (uint32_t)((wm * 64 + (l & 15)) * LDSS + ((l >> 4) << 4));
    uint32_t b_off = (uint32_t)((wn * 64 + ((l >> 4) << 3) + (l & 7)) * LDSS
                                + (((l >> 3) & 1) << 4));
    #pragma unroll
    for (int kk = 0; kk < 2; kk++) {
        uint32_t kb = (uint32_t)(kk * 32);
        uint32_t ah[4][4], bh[8][2];
        #pragma unroll
        for (int m = 0; m < 4; m++)
            ldmx4(ah[m], As + a_off + m * (16 * LDSS) + kb);
        #pragma unroll
        for (int p = 0; p < 4; p++) {
            uint32_t r[4];
            ldmx4(r, Bs + b_off + p * (16 * LDSS) + kb);
            bh[2*p][0] = r[0]; bh[2*p][1] = r[1];
            bh[2*p+1][0] = r[2]; bh[2*p+1][1] = r[3];
        }
        #pragma unroll
        for (int m = 0; m < 4; m++)
            #pragma unroll
            for (int n = 0; n < 8; n++)
                mma16816h(acc[m][n], ah[m], bh[n]);
    }
}

__global__ __launch_bounds__(128) void gemm_pv_kernel()
{
    int z = blockIdx.z, b = z >> 4, h = z & 15, kh = h >> 1;
    const f16* A = g_ph + (long)z * SEQ * SEQ + (long)blockIdx.y * 128 * SEQ;
    const f16* B = g_vth + (long)(b * NKV + kh) * HD * SEQ;
    f16* C = g_ctxh + (long)b * SEQ * DMODEL + h * HD;

    constexpr int S = 3;
    extern __shared__ char smem[];
    uint32_t sb = smem_u32(smem);
    const int tid = threadIdx.x, wid = tid >> 5, l = tid & 31;
    const int wm = wid & 1, wn = wid >> 1;

    float acc[4][8][4];
    #pragma unroll
    for (int m = 0; m < 4; m++)
        #pragma unroll
        for (int n = 0; n < 8; n++)
            #pragma unroll
            for (int i = 0; i < 4; i++) acc[m][n][i] = 0.f;

    const int nk = SEQ >> 5;
    #pragma unroll
    for (int c = 0; c < S - 1; c++) {
        load_stage_h(sb, c, A, B, SEQ, SEQ, c * 32, tid);
        CP_COMMIT();
    }
    int slot_c = 0, slot_p = S - 1;
    for (int c = 0; c < nk; c++) {
        cp_wait<S - 2>();
        __syncthreads();
        if (c + S - 1 < nk)
            load_stage_h(sb, slot_p, A, B, SEQ, SEQ, (c + S - 1) * 32, tid);
        CP_COMMIT();
        compute_stage_h(sb, slot_c, wm, wn, l, acc);
        slot_c = (slot_c + 1 == S) ? 0 : slot_c + 1;
        slot_p = (slot_p + 1 == S) ? 0 : slot_p + 1;
    }

    const int row0 = blockIdx.y * 128 + wm * 64, col0 = wn * 64;
    #pragma unroll
    for (int m = 0; m < 4; m++) {
        int r0 = row0 + m * 16 + (l >> 2);
        #pragma unroll
        for (int n = 0; n < 8; n++) {
            int cc = col0 + n * 8 + (l & 3) * 2;
            __half2 h0, h1;
            h0.x = __float2half(acc[m][n][0]); h0.y = __float2half(acc[m][n][1]);
            h1.x = __float2half(acc[m][n][2]); h1.y = __float2half(acc[m][n][3]);
            *(__half2*)(C + (long)r0 * DMODEL + cc)       = h0;
            *(__half2*)(C + (long)(r0 + 8) * DMODEL + cc) = h1;
        }
    }
}

// ---------------------------------------------------------------------------
// Reductions
// ---------------------------------------------------------------------------
__device__ __forceinline__ float block_reduce_sum(float v)
{
    __shared__ float red[32];
    int lid = threadIdx.x & 31, wid = threadIdx.x >> 5;
    #pragma unroll
    for (int o = 16; o; o >>= 1) v += __shfl_xor_sync(0xffffffffu, v, o);
    if (lid == 0) red[wid] = v;
    __syncthreads();
    v = (threadIdx.x < 8) ? red[threadIdx.x] : 0.f;
    if (wid == 0) {
        #pragma unroll
        for (int o = 4; o; o >>= 1) v += __shfl_xor_sync(0xffffffffu, v, o);
        if (lid == 0) red[0] = v;
    }
    __syncthreads();
    return red[0];
}
__device__ __forceinline__ float block_reduce_max(float v)
{
    __shared__ float red[32];
    int lid = threadIdx.x & 31, wid = threadIdx.x >> 5;
    #pragma unroll
    for (int o = 16; o; o >>= 1) v = fmaxf(v, __shfl_xor_sync(0xffffffffu, v, o));
    if (lid == 0) red[wid] = v;
    __syncthreads();
    v = (threadIdx.x < 8) ? red[threadIdx.x] : -INFINITY;
    if (wid == 0) {
        #pragma unroll
        for (int o = 4; o; o >>= 1) v = fmaxf(v, __shfl_xor_sync(0xffffffffu, v, o));
        if (lid == 0) red[0] = v;
    }
    __syncthreads();
    return red[0];
}

// ---------------------------------------------------------------------------
// RMSNorm -> fp16
// ---------------------------------------------------------------------------
__global__ __launch_bounds__(256) void rmsnorm_f16_kernel(
    const float* __restrict__ x, const float* __restrict__ w,
    f16* __restrict__ oh)
{
    long row = blockIdx.x;
    const float* xr = x + row * DMODEL;
    float vals[8];
    float ss = 0.f;
    #pragma unroll
    for (int i = 0; i < 8; i++) {
        int idx = threadIdx.x + i * 256;
        vals[i] = xr[idx];
        ss = fmaf(vals[i], vals[i], ss);
    }
    float total = block_reduce_sum(ss);
    float rstd = rsqrtf(total * (1.0f / DMODEL) + EPSV);
    #pragma unroll
    for (int i = 0; i < 8; i++) {
        int idx = threadIdx.x + i * 256;
        oh[row * DMODEL + idx] = __float2half(vals[i] * rstd * w[idx]);
    }
}

// ---------------------------------------------------------------------------
// FAST weight transpose: in [RI, CI] fp32 -> out [CI, RI] fp16.
// 64x64 tiles, 256 threads. Convert to f16 at load into smem (stride 65
// f16 -> conflict-free column reads). Output: one warp writes one full
// 64-f16 output row as 32 x half2 = 128B coalesced.
// ---------------------------------------------------------------------------
__global__ __launch_bounds__(256) void transpose_f16_fast(
    const float* __restrict__ in, f16* __restrict__ oh, int RI, int CI)
{
    __shared__ f16 t[64][65];
    const int tid = threadIdx.x;
    const int r0 = blockIdx.y * 64, c0 = blockIdx.x * 64;
    // load 64x64 fp32, convert to f16 in smem
    {
        int row = tid >> 2;           // 0..63
        int q   = tid & 3;            // 0..3
        const float* ip = in + (long)(r0 + row) * CI + c0;
        #pragma unroll
        for (int i = 0; i < 4; i++) {
            int c = q * 4 + i * 16;
            float4 v = *(const float4*)(ip + c);
            t[row][c + 0] = __float2half(v.x);
            t[row][c + 1] = __float2half(v.y);
            t[row][c + 2] = __float2half(v.z);
            t[row][c + 3] = __float2half(v.w);
        }
    }
    __syncthreads();
    // write: output row (c0+c) gets input column c; 64 f16 = 32 half2/warp
    {
        int wid = tid >> 5, lane = tid & 31;
        #pragma unroll
        for (int i = 0; i < 8; i++) {
            int c = wid + i * 8;      // 0..63
            __half2 h;
            h.x = t[2 * lane][c];
            h.y = t[2 * lane + 1][c];
            *(__half2*)(oh + (long)(c0 + c) * RI + r0 + 2 * lane) = h;
        }
    }
}

// V transpose: g_v [b, s, kh*128+d] -> g_vth [(b*8+kh)][d][s] fp16
__global__ __launch_bounds__(256) void vT_kernel()
{
    __shared__ float t[32][33];
    int z = blockIdx.z;
    int b = z >> 3, kh = z & 7;
    const float* in = g_v + (long)b * SEQ * DKV + kh * HD;
    f16* oh = g_vth + (long)z * HD * SEQ;
    int tx = threadIdx.x & 31, ty = threadIdx.x >> 5;
    int s0 = blockIdx.y * 32, d0 = blockIdx.x * 32;
    #pragma unroll
    for (int i = 0; i < 4; i++)
        t[ty + i * 8][tx] = in[(long)(s0 + ty + i * 8) * DKV + d0 + tx];
    __syncthreads();
    #pragma unroll
    for (int i = 0; i < 4; i++)
        oh[(long)(d0 + ty + i * 8) * SEQ + s0 + tx] =
            __float2half(t[tx][ty + i * 8]);
}

// ---------------------------------------------------------------------------
// Softmax (scale + mask), fp16 in -> fp16 out. Fast exp.
// ---------------------------------------------------------------------------
__global__ __launch_bounds__(256) void softmax_kernel(const float* __restrict__ mask)
{
    int z = blockIdx.y;
    int b = z >> 4;
    long row = blockIdx.x;
    const f16* srow = g_sc + ((long)z * SEQ + row) * SEQ;
    const float* mrow = mask + ((long)b * SEQ + row) * SEQ;
    f16* phr = g_ph + ((long)z * SEQ + row) * SEQ;

    float v[8];
    float mx = -INFINITY;
    #pragma unroll
    for (int i = 0; i < 8; i++) {
        int idx = threadIdx.x + i * 256;
        v[i] = fmaf(__half2float(srow[idx]), SM_SCALE, mrow[idx]);
        mx = fmaxf(mx, v[i]);
    }
    float bm = block_reduce_max(mx);
    float sum = 0.f;
    #pragma unroll
    for (int i = 0; i < 8; i++) {
        v[i] = fexpf(v[i] - bm);
        sum += v[i];
    }
    float total = block_reduce_sum(sum);
    float inv = 1.0f / total;
    #pragma unroll
    for (int i = 0; i < 8; i++) {
        int idx = threadIdx.x + i * 256;
        phr[idx] = __float2half(v[i] * inv);
    }
}

// ---------------------------------------------------------------------------
// Launch (ordered so ncu -s 5 -c 1 captures the Q-projection GEMM)
// ---------------------------------------------------------------------------
extern "C" void kernel_launch(void* const* d_in, const int* in_sizes, int n_in,
                              void* d_out, int out_size)
{
    const float* hs   = (const float*)d_in[0];
    const float* cosp = (const float*)d_in[1];
    const float* sinp = (const float*)d_in[2];
    const float* mask = (const float*)d_in[3];
    const float* wq   = (const float*)d_in[4];
    const float* wk   = (const float*)d_in[5];
    const float* wv   = (const float*)d_in[6];
    const float* wo   = (const float*)d_in[7];
    const float* wg   = (const float*)d_in[8];
    const float* wu   = (const float*)d_in[9];
    const float* wd   = (const float*)d_in[10];
    const float* ln1  = (const float*)d_in[11];
    const float* ln2  = (const float*)d_in[12];
    float* out = (float*)d_out;

    cudaFuncSetAttribute(g256_f32out_kernel,
                         cudaFuncAttributeMaxDynamicSharedMemorySize, SM2);
    cudaFuncSetAttribute(g256_f16out_kernel,
                         cudaFuncAttributeMaxDynamicSharedMemorySize, SM2);
    cudaFuncSetAttribute(g256_rope_kernel,
                         cudaFuncAttributeMaxDynamicSharedMemorySize, SM2);
    cudaFuncSetAttribute(g256_silu_kernel,
                         cudaFuncAttributeMaxDynamicSharedMemorySize, SM2);
    cudaFuncSetAttribute(g256_scores_kernel,
                         cudaFuncAttributeMaxDynamicSharedMemorySize, SM2);
    cudaFuncSetAttribute(gemm_pv_kernel,
                         cudaFuncAttributeMaxDynamicSharedMemorySize, SM1);

    f16 *x1h, *qh, *kh, *ctxh, *x2h, *g16, *mh;
    f16 *wqt, *wkt, *wvt, *wot, *wgt, *wut, *wdt;
    float *v, *h2;
    cudaGetSymbolAddress((void**)&x1h, g_x1h);
    cudaGetSymbolAddress((void**)&qh,  g_qh);
    cudaGetSymbolAddress((void**)&kh,  g_kh);
    cudaGetSymbolAddress((void**)&ctxh,g_ctxh);
    cudaGetSymbolAddress((void**)&x2h, g_x2h);
    cudaGetSymbolAddress((void**)&g16, g_g16);
    cudaGetSymbolAddress((void**)&mh,  g_mh);
    cudaGetSymbolAddress((void**)&wqt, g_wqt);
    cudaGetSymbolAddress((void**)&wkt, g_wkt);
    cudaGetSymbolAddress((void**)&wvt, g_wvt);
    cudaGetSymbolAddress((void**)&wot, g_wot);
    cudaGetSymbolAddress((void**)&wgt, g_wgt);
    cudaGetSymbolAddress((void**)&wut, g_wut);
    cudaGetSymbolAddress((void**)&wdt, g_wdt);
    cudaGetSymbolAddress((void**)&v,   g_v);
    cudaGetSymbolAddress((void**)&h2,  g_h2);

    // 1) x1 = rmsnorm(hs) -> fp16
    rmsnorm_f16_kernel<<<TOK, 256>>>(hs, ln1, x1h);

    // 2-5) attention weight transposes (fast path)
    transpose_f16_fast<<<dim3(DMODEL/64, DMODEL/64), 256>>>(wq, wqt, DMODEL, DMODEL);
    transpose_f16_fast<<<dim3(DKV/64,    DMODEL/64), 256>>>(wk, wkt, DMODEL, DKV);
    transpose_f16_fast<<<dim3(DKV/64,    DMODEL/64), 256>>>(wv, wvt, DMODEL, DKV);
    transpose_f16_fast<<<dim3(DMODEL/64, DMODEL/64), 256>>>(wo, wot, DMODEL, DMODEL);

    // 6) Q projection + fused RoPE  <-- ncu -s 5 captures this launch
    g256_rope_kernel<<<dim3(DMODEL/256, TOK/128), 256, SM2>>>(
        x1h, DMODEL, wqt, DMODEL, qh, DMODEL, DMODEL, cosp, sinp);
    // 7-8) K projection + RoPE; V projection
    g256_rope_kernel<<<dim3(DKV/256, TOK/128), 256, SM2>>>(
        x1h, DMODEL, wkt, DMODEL, kh, DKV, DMODEL, cosp, sinp);
    g256_f32out_kernel<<<dim3(DKV/256, TOK/128), 256, SM2>>>(
        x1h, DMODEL, wvt, DMODEL, nullptr, v, DKV, DMODEL);

    // 9-11) MLP weight transposes (fast path)
    transpose_f16_fast<<<dim3(DFF/64,    DMODEL/64), 256>>>(wg, wgt, DMODEL, DFF);
    transpose_f16_fast<<<dim3(DFF/64,    DMODEL/64), 256>>>(wu, wut, DMODEL, DFF);
    transpose_f16_fast<<<dim3(DMODEL/64, DFF/64),    256>>>(wd, wdt, DFF, DMODEL);

    // 12) V transpose -> fp16
    vT_kernel<<<dim3(HD/32, SEQ/32, BATCH*NKV), 256>>>();

    // 13) scores = Q K^T -> fp16
    g256_scores_kernel<<<dim3(SEQ/256, SEQ/128, BATCH*NHEADS), 256, SM2>>>();

    // 14) softmax -> P fp16
    softmax_kernel<<<dim3(SEQ, BATCH*NHEADS), 256>>>(mask);

    // 15) ctx = P V -> fp16
    gemm_pv_kernel<<<dim3(1, SEQ/128, BATCH*NHEADS), 128, SM1>>>();

    // 16) h2 = hs + ctx @ wo
    g256_f32out_kernel<<<dim3(DMODEL/256, TOK/128), 256, SM2>>>(
        ctxh, DMODEL, wot, DMODEL, hs, h2, DMODEL, DMODEL);

    // 17) x2 = rmsnorm(h2) -> fp16
    rmsnorm_f16_kernel<<<TOK, 256>>>(h2, ln2, x2h);

    // 18-19) MLP: gate, then up with fused SwiGLU
    g256_f16out_kernel<<<dim3(DFF/256, TOK/128), 256, SM2>>>(
        x2h, DMODEL, wgt, DMODEL, g16, DFF, DMODEL);
    g256_silu_kernel<<<dim3(DFF/256, TOK/128), 256, SM2>>>(
        x2h, DMODEL, wut, DMODEL, mh, DFF, DMODEL, g16);

    // 20) out = h2 + m @ wd
    g256_f32out_kernel<<<dim3(DMODEL/256, TOK/128), 256, SM2>>>(
        mh, DFF, wdt, DFF, h2, out, DMODEL, DFF);
}